// round 1
// baseline (speedup 1.0000x reference)
#include <cuda_runtime.h>
#include <cuda_bf16.h>
#include <math.h>

#define VOCAB   50257
#define DIM     768
#define RANK    16
#define SCALING 2.0f

#define NB1     148         // kernel-1 blocks (1 per SM, perfect wave)
#define ROWS1   340         // rows per k1 block (148*340 >= 50257)
#define SH1STR  344         // shared A stride (floats), 8B-aligned rows

#define K3_BLOCKS 128
#define K3_TOK    128       // tokens per k3 block (128*128 = 16384)
#define SH3STR    136       // padded stride for shAg

typedef unsigned long long u64;

// ---------------- scratch (no allocations allowed) ----------------
__device__ __align__(16) float g_partM[NB1 * DIM * RANK];   // [b][d*16+r]
__device__ __align__(16) float g_partE2[NB1 * DIM];
__device__ __align__(16) float g_partG[NB1 * 256];
__device__ __align__(16) float g_M[DIM * RANK];             // [d*16+r]
__device__ __align__(16) float g_E2[DIM];
__device__ __align__(16) float g_G[256];
__device__ __align__(16) float g_sc[DIM];                   // magnitude/norm
__device__ __align__(16) float g_Bs[RANK * DIM];            // s*B*sc

// ---------------- f32x2 helpers ----------------
__device__ __forceinline__ u64 pack2(float lo, float hi) {
    u64 r;
    asm("mov.b64 %0, {%1, %2};" : "=l"(r) : "f"(lo), "f"(hi));
    return r;
}
__device__ __forceinline__ void unpack2(u64 v, float& lo, float& hi) {
    asm("mov.b64 {%0, %1}, %2;" : "=f"(lo), "=f"(hi) : "l"(v));
}
__device__ __forceinline__ u64 fma2(u64 a, u64 b, u64 c) {
    u64 d;
    asm("fma.rn.f32x2 %0, %1, %2, %3;" : "=l"(d) : "l"(a), "l"(b), "l"(c));
    return d;
}
__device__ __forceinline__ u64 mul2(u64 a, u64 b) {
    u64 d;
    asm("mul.rn.f32x2 %0, %1, %2;" : "=l"(d) : "l"(a), "l"(b));
    return d;
}

// =================================================================
// Kernel 1: stream E once; per-block partials of
//   E2[d]   = sum_v E[v,d]^2
//   M[d,r]  = sum_v E[v,d]*A[v,r]
//   G[r,r'] = sum_v A[v,r]*A[v,r']
// 768 threads, 1 column per thread, f32x2 over row pairs,
// 8-row register prefetch to hide DRAM latency.
// =================================================================
__global__ __launch_bounds__(768, 1)
void k1_stats(const float* __restrict__ E, const float* __restrict__ A) {
    __shared__ __align__(16) float shA[RANK][SH1STR];
    const int b   = blockIdx.x;
    const int tid = threadIdx.x;
    const int v0  = b * ROWS1;
    const int rows = min(ROWS1, VOCAB - v0);

    // stage A chunk into shared, transposed: shA[r][i] = A[v0+i, r]
    for (int idx = tid; idx < rows * RANK; idx += 768) {
        int i = idx >> 4, r = idx & 15;
        shA[r][i] = A[(size_t)(v0 + i) * RANK + r];
    }
    __syncthreads();

    const float* cp = E + (size_t)v0 * DIM + tid;   // this thread's column

    u64 accM[RANK];
    u64 accE = 0ull;
#pragma unroll
    for (int r = 0; r < RANK; r++) accM[r] = 0ull;

    const int full8 = rows & ~7;

    float cur[8];
#pragma unroll
    for (int k = 0; k < 8; k++) cur[k] = cp[(size_t)k * DIM];

    for (int base = 0; base < full8; base += 8) {
        // prefetch next 8 rows (clamped; clamped values never consumed)
        float nxt[8];
#pragma unroll
        for (int k = 0; k < 8; k++) {
            int idx = base + 8 + k;
            idx = min(idx, rows - 1);
            nxt[k] = cp[(size_t)idx * DIM];
        }
#pragma unroll
        for (int p = 0; p < 4; p++) {
            const int i = base + 2 * p;
            u64 e = pack2(cur[2 * p], cur[2 * p + 1]);
            accE = fma2(e, e, accE);
#pragma unroll
            for (int r = 0; r < RANK; r++) {
                u64 a2 = *reinterpret_cast<const u64*>(&shA[r][i]);
                accM[r] = fma2(a2, e, accM[r]);
            }
        }
#pragma unroll
        for (int k = 0; k < 8; k++) cur[k] = nxt[k];
    }
    // scalar tail (< 8 rows)
    for (int i = full8; i < rows; i++) {
        float ev = cp[(size_t)i * DIM];
        u64 e = pack2(ev, 0.f);
        accE = fma2(e, e, accE);
#pragma unroll
        for (int r = 0; r < RANK; r++) {
            u64 a2 = pack2(shA[r][i], 0.f);
            accM[r] = fma2(a2, e, accM[r]);
        }
    }

    // collapse f32x2 lanes and write partials (coalesced float4)
    float mloc[RANK];
#pragma unroll
    for (int r = 0; r < RANK; r++) {
        float lo, hi;
        unpack2(accM[r], lo, hi);
        mloc[r] = lo + hi;
    }
    {
        float4* pM = reinterpret_cast<float4*>(g_partM + (size_t)b * (DIM * RANK) + tid * RANK);
#pragma unroll
        for (int q = 0; q < 4; q++)
            pM[q] = make_float4(mloc[4 * q], mloc[4 * q + 1], mloc[4 * q + 2], mloc[4 * q + 3]);
    }
    {
        float lo, hi;
        unpack2(accE, lo, hi);
        g_partE2[b * DIM + tid] = lo + hi;
    }

    // Gram partials (cheap tail; threads 0..255 each own one (r,r') pair)
    if (tid < 256) {
        int r = tid >> 4, r2 = tid & 15;
        float g = 0.f;
        for (int i = 0; i < rows; i++)
            g += shA[r][i] * shA[r2][i];
        g_partG[b * 256 + tid] = g;
    }
}

// =================================================================
// Kernel 2: deterministic reduction of the 148 partials.
// grid 52 x 256 = 13312 threads = 12288 (M) + 768 (E2) + 256 (G)
// =================================================================
__global__ void k2_reduce() {
    int j = blockIdx.x * 256 + threadIdx.x;
    if (j < DIM * RANK) {
        float s = 0.f;
#pragma unroll 4
        for (int b = 0; b < NB1; b++) s += g_partM[(size_t)b * (DIM * RANK) + j];
        g_M[j] = s;
    } else if (j < DIM * RANK + DIM) {
        int d = j - DIM * RANK;
        float s = 0.f;
#pragma unroll 4
        for (int b = 0; b < NB1; b++) s += g_partE2[b * DIM + d];
        g_E2[d] = s;
    } else {
        int t = j - (DIM * RANK + DIM);
        float s = 0.f;
#pragma unroll 4
        for (int b = 0; b < NB1; b++) s += g_partG[b * 256 + t];
        g_G[t] = s;
    }
}

// =================================================================
// Kernel 2b: per-column norm -> sc[d] = mag[d]/norm[d], and
// Bs[r,d] = SCALING * B[r,d] * sc[d].   grid 3 x 256 (= 768 cols)
// =================================================================
__global__ void k2b_norms(const float* __restrict__ B, const float* __restrict__ mag) {
    int d = blockIdx.x * 256 + threadIdx.x;
    float bb[RANK];
#pragma unroll
    for (int r = 0; r < RANK; r++) bb[r] = B[r * DIM + d];
    float cross = 0.f, quad = 0.f;
#pragma unroll
    for (int r = 0; r < RANK; r++) {
        float t = 0.f;
#pragma unroll
        for (int r2 = 0; r2 < RANK; r2++) t += g_G[r * RANK + r2] * bb[r2];
        quad  += bb[r] * t;
        cross += g_M[d * RANK + r] * bb[r];
    }
    float n2 = g_E2[d] + 2.f * SCALING * cross + SCALING * SCALING * quad;
    float n  = fmaxf(sqrtf(n2), 1e-8f);
    float sc = mag[d] / n;
    g_sc[d] = sc;
#pragma unroll
    for (int r = 0; r < RANK; r++) g_Bs[r * DIM + d] = SCALING * bb[r] * sc;
}

// =================================================================
// Kernel 3: gather.  out[t,d] = E[v,d]*sc[d] + sum_r A[v,r]*Bs[r,d]
// 768 threads (1 column each), Bs duplicated in registers as f32x2,
// 2 tokens per f32x2, 8-token prefetch, A rows staged in shared.
// =================================================================
__global__ __launch_bounds__(768, 1)
void k3_gather(const int* __restrict__ ids, const float* __restrict__ E,
               const float* __restrict__ A, float* __restrict__ out) {
    __shared__ int shT[K3_TOK];
    __shared__ __align__(16) float shAg[RANK][SH3STR];
    const int b   = blockIdx.x;
    const int tid = threadIdx.x;
    const int t0  = b * K3_TOK;
    const int d   = tid;

    // Bs + sc duplicated into f32x2 registers for this column
    u64 rb[RANK], scd;
#pragma unroll
    for (int r = 0; r < RANK; r++) {
        float x = g_Bs[r * DIM + d];
        rb[r] = pack2(x, x);
    }
    {
        float s = g_sc[d];
        scd = pack2(s, s);
    }

    if (tid < K3_TOK) shT[tid] = ids[t0 + tid];
    __syncthreads();
    for (int idx = tid; idx < K3_TOK * RANK; idx += 768) {
        int i = idx >> 4, r = idx & 15;
        shAg[r][i] = A[(size_t)shT[i] * RANK + r];
    }
    __syncthreads();

    float cur[8];
#pragma unroll
    for (int k = 0; k < 8; k++) cur[k] = E[(size_t)shT[k] * DIM + d];

    for (int base = 0; base < K3_TOK; base += 8) {
        float nxt[8];
        const int nb = (base + 8 < K3_TOK) ? base + 8 : base;  // last iter: redundant re-load (harmless)
#pragma unroll
        for (int k = 0; k < 8; k++)
            nxt[k] = E[(size_t)shT[nb + k] * DIM + d];
#pragma unroll
        for (int p = 0; p < 4; p++) {
            const int i = base + 2 * p;
            u64 e   = pack2(cur[2 * p], cur[2 * p + 1]);
            u64 acc = mul2(e, scd);
#pragma unroll
            for (int r = 0; r < RANK; r++) {
                u64 a2 = *reinterpret_cast<const u64*>(&shAg[r][i]);
                acc = fma2(a2, rb[r], acc);
            }
            float lo, hi;
            unpack2(acc, lo, hi);
            out[(size_t)(t0 + i) * DIM + d]     = lo;
            out[(size_t)(t0 + i + 1) * DIM + d] = hi;
        }
#pragma unroll
        for (int k = 0; k < 8; k++) cur[k] = nxt[k];
    }
}

// =================================================================
extern "C" void kernel_launch(void* const* d_in, const int* in_sizes, int n_in,
                              void* d_out, int out_size) {
    const int*   ids = (const int*)d_in[0];    // [8,2048] int32
    const float* E   = (const float*)d_in[1];  // [50257,768]
    const float* A   = (const float*)d_in[2];  // [50257,16]
    const float* B   = (const float*)d_in[3];  // [16,768]
    const float* mag = (const float*)d_in[4];  // [768]
    float* out = (float*)d_out;                // [8,2048,768] fp32

    k1_stats <<<NB1, 768>>>(E, A);
    k2_reduce<<<52, 256>>>();
    k2b_norms<<<3, 256>>>(B, mag);
    k3_gather<<<K3_BLOCKS, 768>>>(ids, E, A, out);
}